// round 16
// baseline (speedup 1.0000x reference)
#include <cuda_runtime.h>
#include <cuda_fp16.h>
#include <math.h>
#include <float.h>
#include <stdint.h>

#define BATCH 4
#define NPTS 4096
#define PTOT (BATCH * NPTS)
#define KNNK 16
#define CIN 9
#define CH 128
#define NCLS 13

__device__ __forceinline__ uint32_t s2u(const void* p) {
    return (uint32_t)__cvta_generic_to_shared(p);
}
__device__ __forceinline__ void ldsm4(uint32_t* r, uint32_t a) {
    asm volatile("ldmatrix.sync.aligned.m8n8.x4.shared.b16 {%0,%1,%2,%3}, [%4];"
                 : "=r"(r[0]), "=r"(r[1]), "=r"(r[2]), "=r"(r[3]) : "r"(a));
}
__device__ __forceinline__ void mma16816(float* d, const uint32_t* a, const uint32_t* b) {
    asm volatile("mma.sync.aligned.m16n8k16.row.col.f32.f16.f16.f32 "
                 "{%0,%1,%2,%3}, {%4,%5,%6,%7}, {%8,%9}, {%0,%1,%2,%3};"
                 : "+f"(d[0]), "+f"(d[1]), "+f"(d[2]), "+f"(d[3])
                 : "r"(a[0]), "r"(a[1]), "r"(a[2]), "r"(a[3]), "r"(b[0]), "r"(b[1]));
}
// monotone float<->uint key (for atomicMax on signed floats)
__device__ __forceinline__ unsigned fkey(float f) {
    unsigned u = __float_as_uint(f);
    return (u & 0x80000000u) ? ~u : (u | 0x80000000u);
}
__device__ __forceinline__ float funkey(unsigned k) {
    unsigned u = (k & 0x80000000u) ? (k & 0x7fffffffu) : ~k;
    return __uint_as_float(u);
}

// ---------------- scratch pool (floats) -------------------------------------
#define OFF_IDX   0
#define OFF_E1    (OFF_IDX  + PTOT * 16)
#define OFF_XCUR  (OFF_E1   + PTOT * 64)
#define OFF_QKV   (OFF_XCUR + PTOT * 64)
#define OFF_AGG   (OFF_QKV  + PTOT * 192)
#define OFF_XCAT  (OFF_AGG  + PTOT * 64)
#define OFF_FUSE  (OFF_XCAT + PTOT * 192)
#define OFF_G     (OFF_FUSE + PTOT * 512)
#define OFF_BEFF  (OFF_G    + BATCH * 2048)
#define OFF_C1    (OFF_BEFF + BATCH * 512)
#define OFF_C2    (OFF_C1   + PTOT * 256)
#define OFF_WE2   (OFF_C2   + PTOT * 128)
#define OFF_WQKV  (OFF_WE2  + 8192)
#define OFF_WWO   (OFF_WQKV + 73728)
#define OFF_WFUSE (OFF_WWO  + 24576)
#define OFF_WC1   (OFF_WFUSE + 196608)
#define OFF_WC2   (OFF_WC1  + 262144)
#define OFF_GPART (OFF_WC2  + 65536)        // 2 * 4*1024*32 = 262144
#define POOL_SZ   (OFF_GPART + 262144)

__device__ __align__(16) float g_pool[POOL_SZ];

// ---------------- KNN device routine (one warp per point) -------------------
__device__ void knn_warp(const float* __restrict__ in, int* __restrict__ idxo,
                         int gw, int lane) {
    int b = gw >> 12, n = gw & (NPTS - 1);
    const float* xb = in + (size_t)b * CIN * NPTS;
    float x0 = xb[n], y0 = xb[NPTS + n], z0 = xb[2 * NPTS + n];
    float sq0 = x0 * x0 + y0 * y0 + z0 * z0;
    float dl[KNNK]; int il[KNNK];
    #pragma unroll
    for (int t = 0; t < KNNK; t++) { dl[t] = FLT_MAX; il[t] = 0x7fffffff; }
    float worst = FLT_MAX;
    for (int i = 0; i < NPTS / 32; i++) {
        int m = i * 32 + lane;
        float xm = xb[m], ym = xb[NPTS + m], zm = xb[2 * NPTS + m];
        float sqm = xm * xm + ym * ym + zm * zm;
        float dot = x0 * xm + y0 * ym + z0 * zm;
        float dm = sq0 + sqm - 2.0f * dot;
        if (dm < worst) {
            bool done = false;
            #pragma unroll
            for (int t = 0; t < KNNK; t++)
                if (!done && dl[t] == worst) { dl[t] = dm; il[t] = m; done = true; }
            worst = dl[0];
            #pragma unroll
            for (int t = 1; t < KNNK; t++) worst = fmaxf(worst, dl[t]);
        }
    }
    int* op = idxo + (size_t)gw * KNNK;
    for (int t = 0; t < KNNK; t++) {
        float lm = dl[0]; int li = il[0];
        #pragma unroll
        for (int j = 1; j < KNNK; j++)
            if (dl[j] < lm || (dl[j] == lm && il[j] < li)) { lm = dl[j]; li = il[j]; }
        float bm = lm; int bi = li;
        #pragma unroll
        for (int off = 16; off > 0; off >>= 1) {
            float om = __shfl_down_sync(0xffffffffu, bm, off);
            int   oi = __shfl_down_sync(0xffffffffu, bi, off);
            if (om < bm || (om == bm && oi < bi)) { bm = om; bi = oi; }
        }
        bm = __shfl_sync(0xffffffffu, bm, 0);
        bi = __shfl_sync(0xffffffffu, bi, 0);
        if (lane == 0) op[t] = bi;
        if (bi == li && bm == lm) {
            #pragma unroll
            for (int j = 0; j < KNNK; j++) if (il[j] == bi) dl[j] = FLT_MAX;
        }
    }
}

// ---------------- fused pack + emb1 + knn kernel ----------------------------
#define PS0 16384
#define PS1 (PS0 + 147456)
#define PS2 (PS1 + 49152)
#define PS3 (PS2 + 393216)
#define PS4 (PS3 + 524288)
#define PS5 (PS4 + 131072)
#define PS6 (PS5 + PTOT * 128)
#define NBE (PS6 / 256)
#define NBK (PTOT / 8)
__global__ void pack_all_kernel(
    const float* __restrict__ inp,
    const float* __restrict__ e1w, const float* __restrict__ e1s, const float* __restrict__ e1b,
    const float* __restrict__ e2w,
    const float* __restrict__ wq, const float* __restrict__ wk, const float* __restrict__ wv,
    const float* __restrict__ wo, const float* __restrict__ fw,
    const float* __restrict__ c1w, const float* __restrict__ c2w,
    __half* __restrict__ we2, __half* __restrict__ wqkv,
    __half* __restrict__ wwo, __half* __restrict__ wfuse,
    __half* __restrict__ wc1, __half* __restrict__ wc2,
    __half* __restrict__ e1, int* __restrict__ idxo) {
    if (blockIdx.x >= NBE) {
        int gw = (blockIdx.x - NBE) * 8 + (threadIdx.x >> 5);
        knn_warp(inp, idxo, gw, threadIdx.x & 31);
        return;
    }
    int i = blockIdx.x * 256 + threadIdx.x;
    if (i < PS0) {
        we2[i] = __float2half(e2w[i]);
    } else if (i < PS1) {
        int j = i - PS0;
        int blk = j / 49152, t = j % 49152;
        int o = t / CH, k = t % CH;
        const float* src = (o < CH) ? wq : (o < 2 * CH) ? wk : wv;
        int oo = o & (CH - 1);
        wqkv[j] = __float2half(src[(size_t)blk * CH * CH + (size_t)oo * CH + k]);
    } else if (i < PS2) {
        int j = i - PS1;
        wwo[j] = __float2half(wo[j]);
    } else if (i < PS3) {
        int j = i - PS2;
        wfuse[j] = __float2half(fw[j]);
    } else if (i < PS4) {
        int j = i - PS3;
        int o = j >> 10, k = j & 1023;
        wc1[j] = __float2half(c1w[(size_t)o * 3072 + k]);
    } else if (i < PS5) {
        int j = i - PS4;
        wc2[j] = __float2half(c2w[j]);
    } else {
        int j = i - PS5;
        int o = j & 127, p = j >> 7;
        int b = p >> 12, n = p & (NPTS - 1);
        const float* xb = inp + (size_t)b * CIN * NPTS + n;
        const float* wr = e1w + o * CIN;
        float acc = 0.f;
        #pragma unroll
        for (int c = 0; c < CIN; c++) acc = fmaf(wr[c], xb[(size_t)c * NPTS], acc);
        float z = fmaxf(e1s[o] * acc + e1b[o], 0.f);
        e1[j] = __float2half(z);
    }
}

// ---------------- fp16 HMMA GEMM (R10 core), Kd % 64 == 0 assumed -----------
template<int MT, bool POOL>
__global__ __launch_bounds__(256, 3)
void gemm_hmma_kernel(const __half* __restrict__ X, const __half* __restrict__ W,
                      const float* __restrict__ b1, const float* __restrict__ addb,
                      const float* __restrict__ s, const float* __restrict__ sh,
                      const __half* __restrict__ resid,
                      __half* __restrict__ out, __half* __restrict__ out2,
                      int Kd, int ldx, int ldr, int Od, int ldo, int ldo2, int act,
                      float* __restrict__ gpart) {
    const int BM = MT * 64;
    const int A_BYTES = BM * 128;
    const int STAGE = A_BYTES + 8192;
    extern __shared__ char smem[];
    uint32_t sb = s2u(smem);
    int tid = threadIdx.x;
    int m0 = blockIdx.x * BM, o0 = blockIdx.y * 64;
    int warp = tid >> 5, lane = tid & 31;
    int warpM = warp & 3, warpN = warp >> 2;
    float acc[MT][4][4];
    #pragma unroll
    for (int a = 0; a < MT; a++)
        #pragma unroll
        for (int bq = 0; bq < 4; bq++)
            #pragma unroll
            for (int c = 0; c < 4; c++) acc[a][bq][c] = 0.f;

    int nkb = Kd >> 6;   // Kd % 64 == 0 for all call sites

    auto load_stage = [&](int kb, int buf) {
        int k0 = kb << 6;
        uint32_t smA = sb + buf * STAGE;
        uint32_t smB = smA + A_BYTES;
        #pragma unroll
        for (int i = tid; i < BM * 8; i += 256) {
            int r = i >> 3, j = i & 7;
            uint32_t doff = r * 128 + ((j ^ (r & 7)) << 4);
            const void* srcA = X + (size_t)(m0 + r) * ldx + k0 + j * 8;
            asm volatile("cp.async.ca.shared.global [%0], [%1], 16;"
                         :: "r"(smA + doff), "l"(srcA));
        }
        #pragma unroll
        for (int i = tid; i < 512; i += 256) {
            int r = i >> 3, j = i & 7;
            uint32_t doff = r * 128 + ((j ^ (r & 7)) << 4);
            const void* srcB = W + (size_t)(o0 + r) * Kd + k0 + j * 8;
            asm volatile("cp.async.ca.shared.global [%0], [%1], 16;"
                         :: "r"(smB + doff), "l"(srcB));
        }
        asm volatile("cp.async.commit_group;");
    };

    load_stage(0, 0);
    if (nkb > 1) load_stage(1, 1);

    for (int kb = 0; kb < nkb; kb++) {
        int buf = kb % 3;
        if (kb + 1 < nkb) asm volatile("cp.async.wait_group 1;");
        else              asm volatile("cp.async.wait_group 0;");
        __syncthreads();
        if (kb + 2 < nkb) load_stage(kb + 2, (kb + 2) % 3);
        uint32_t smA = sb + buf * STAGE;
        uint32_t smB = smA + A_BYTES;

        uint32_t bbuf[2][4][2];
        auto loadB = [&](int kk, int sel) {
            int brow = (lane & 7) + ((lane >> 4) << 3);
            int bjc = (kk >> 3) + ((lane >> 3) & 1);
            #pragma unroll
            for (int nh = 0; nh < 2; nh++) {
                int nr = warpN * 32 + nh * 16 + brow;
                uint32_t r4[4];
                ldsm4(r4, smB + nr * 128 + ((bjc ^ (nr & 7)) << 4));
                bbuf[sel][nh * 2][0] = r4[0]; bbuf[sel][nh * 2][1] = r4[1];
                bbuf[sel][nh * 2 + 1][0] = r4[2]; bbuf[sel][nh * 2 + 1][1] = r4[3];
            }
        };
        loadB(0, 0);
        #pragma unroll
        for (int step = 0; step < 4; step++) {
            int kk = step * 16;
            uint32_t a[MT][4];
            int arow = lane & 15;
            int ajc = (kk >> 3) + (lane >> 4);
            #pragma unroll
            for (int mt = 0; mt < MT; mt++) {
                int mr = warpM * (MT * 16) + mt * 16 + arow;
                ldsm4(a[mt], smA + mr * 128 + ((ajc ^ (mr & 7)) << 4));
            }
            if (step < 3) loadB(kk + 16, (step + 1) & 1);
            #pragma unroll
            for (int mt = 0; mt < MT; mt++)
                #pragma unroll
                for (int nt = 0; nt < 4; nt++)
                    mma16816(acc[mt][nt], a[mt], bbuf[step & 1][nt]);
        }
        __syncthreads();
    }

    // epilogue
    float lmax[POOL ? 8 : 1], lsum[POOL ? 8 : 1];
    if (POOL) {
        #pragma unroll
        for (int ci = 0; ci < 8; ci++) { lmax[ci] = -FLT_MAX; lsum[ci] = 0.f; }
    }
    int r0w = warpM * (MT * 16) + (lane >> 2);
    int c0w = o0 + warpN * 32 + (lane & 3) * 2;
    #pragma unroll
    for (int mt = 0; mt < MT; mt++) {
        #pragma unroll
        for (int i2 = 0; i2 < 2; i2++) {
            int row = m0 + r0w + mt * 16 + i2 * 8;
            int bidx = row >> 12;
            #pragma unroll
            for (int nt = 0; nt < 4; nt++) {
                #pragma unroll
                for (int j = 0; j < 2; j++) {
                    int o = c0w + nt * 8 + j;
                    float y = acc[mt][nt][i2 * 2 + j];
                    float pre = y + (b1 ? b1[o] : 0.f) + (addb ? addb[bidx * Od + o] : 0.f);
                    float z = (s ? s[o] : 1.f) * pre + (sh ? sh[o] : 0.f);
                    if (act == 1) z = fmaxf(z, 0.f);
                    else if (act == 2) z = (z > 0.f) ? z : 0.2f * z;
                    if (resid) z += __half2float(resid[(size_t)row * ldr + o]);
                    if (POOL) {
                        int ci = nt * 2 + j;
                        lmax[ci] = fmaxf(lmax[ci], z);
                        lsum[ci] += z;
                    }
                    __half hz = __float2half(z);
                    out[(size_t)row * ldo + o] = hz;
                    if (out2) out2[(size_t)row * ldo2 + o] = hz;
                }
            }
        }
    }
    if (POOL) {
        unsigned* smax = (unsigned*)smem;
        float* ssum = (float*)smem + 64;
        if (tid < 64) { smax[tid] = 0u; ssum[tid] = 0.f; }
        __syncthreads();
        #pragma unroll
        for (int ci = 0; ci < 8; ci++) {
            int col = warpN * 32 + (lane & 3) * 2 + (ci >> 1) * 8 + (ci & 1);
            atomicMax(&smax[col], fkey(lmax[ci]));
            atomicAdd(&ssum[col], lsum[ci]);
        }
        __syncthreads();
        if (tid < 64) {
            int b = m0 >> 12, mi = (m0 >> 7) & 31;
            int o = o0 + tid;
            size_t base = (size_t)(b * 1024 + o) * 32 + mi;
            gpart[base] = funkey(smax[tid]);
            gpart[131072 + base] = ssum[tid];
        }
    }
}

// ---------------- reduce pooled partials (deterministic order) --------------
__global__ void gfinal_kernel(const float* __restrict__ gpart, float* __restrict__ g) {
    int i = blockIdx.x * 256 + threadIdx.x;   // b*1024+ch, 4096 total
    if (i >= 4096) return;
    const float* pm = gpart + (size_t)i * 32;
    const float* ps = gpart + 131072 + (size_t)i * 32;
    float mx = -FLT_MAX, sm = 0.f;
    #pragma unroll
    for (int t = 0; t < 32; t++) { mx = fmaxf(mx, pm[t]); sm += ps[t]; }
    int b = i >> 10, ch = i & 1023;
    g[b * 2048 + ch] = mx;
    g[b * 2048 + 1024 + ch] = sm * (1.f / 4096.f);
}

// ---------------- attention: 2 points / 128-thread block, half2 -------------
__global__ __launch_bounds__(128)
void attn_agg_kernel(const __half* __restrict__ qkv, const int* __restrict__ idx,
                     const float* __restrict__ in, const float* __restrict__ wpos,
                     __half* __restrict__ agg) {
    int tid = threadIdx.x;
    int h = tid >> 6;
    int l = tid & 63;
    int w2 = l >> 5, lane = l & 31;
    int p = blockIdx.x * 2 + h;
    int b = p >> 12, n = p & (NPTS - 1);
    __shared__ float attnS[2][KNNK], slogS[2][KNNK], relS[2][KNNK][3];
    __shared__ int sIdxS[2][KNNK];

    if (l < KNNK) sIdxS[h][l] = idx[(size_t)p * KNNK + l];
    const half2* q2p = (const half2*)(qkv + (size_t)p * 384);
    half2 q2[2];
    q2[0] = q2p[lane];
    q2[1] = q2p[lane + 32];
    __syncthreads();

    const float* xb = in + (size_t)b * CIN * NPTS;
    #pragma unroll
    for (int i = 0; i < 8; i++) {
        int kk = w2 * 8 + i;
        int m = sIdxS[h][kk];
        const half2* k2p = (const half2*)(qkv + ((size_t)b * NPTS + m) * 384 + CH);
        float d = 0.f;
        #pragma unroll
        for (int u = 0; u < 2; u++) {
            float2 fq = __half22float2(q2[u]);
            float2 fk = __half22float2(k2p[lane + 32 * u]);
            d = fmaf(fq.x, fk.x, d);
            d = fmaf(fq.y, fk.y, d);
        }
        #pragma unroll
        for (int st = 16; st > 0; st >>= 1) d += __shfl_down_sync(0xffffffffu, d, st);
        if (lane == 0) slogS[h][kk] = d * 0.08838834764831845f;
        if (lane < 3)  relS[h][kk][lane] = xb[lane * NPTS + n] - xb[lane * NPTS + m];
    }
    __syncthreads();
    if (w2 == 0) {
        float sv = (lane < KNNK) ? slogS[h][lane] : -FLT_MAX;
        float mx = sv;
        #pragma unroll
        for (int off = 8; off > 0; off >>= 1)
            mx = fmaxf(mx, __shfl_xor_sync(0xffffffffu, mx, off));
        float e = (lane < KNNK) ? expf(sv - mx) : 0.f;
        float sum = e;
        #pragma unroll
        for (int off = 8; off > 0; off >>= 1)
            sum += __shfl_xor_sync(0xffffffffu, sum, off);
        if (lane < KNNK) attnS[h][lane] = e / sum;
    }
    __syncthreads();
    int t = l;
    float w00 = wpos[(2 * t) * 3 + 0], w01 = wpos[(2 * t) * 3 + 1], w02 = wpos[(2 * t) * 3 + 2];
    float w10 = wpos[(2 * t + 1) * 3 + 0], w11 = wpos[(2 * t + 1) * 3 + 1], w12 = wpos[(2 * t + 1) * 3 + 2];
    float a0 = 0.f, a1 = 0.f;
    #pragma unroll
    for (int kk = 0; kk < KNNK; kk++) {
        int m = sIdxS[h][kk];
        float aw = attnS[h][kk];
        float r0 = relS[h][kk][0], r1 = relS[h][kk][1], r2 = relS[h][kk][2];
        half2 v2 = ((const half2*)qkv)[(size_t)(b * NPTS + m) * 192 + 128 + t];
        float2 fv = __half22float2(v2);
        float vn0 = fv.x + w00 * r0 + w01 * r1 + w02 * r2;
        float vn1 = fv.y + w10 * r0 + w11 * r1 + w12 * r2;
        a0 = fmaf(aw, vn0, a0);
        a1 = fmaf(aw, vn1, a1);
    }
    ((half2*)agg)[(size_t)p * 64 + t] = __floats2half2_rn(a0, a1);
}

// ------- fold global features into per-(b,o) cls1 bias (warp per o) ---------
__global__ void beff_kernel(const float* __restrict__ w1, const float* __restrict__ bias1,
                            const float* __restrict__ g, float* __restrict__ beff) {
    int warp = threadIdx.x >> 5, lane = threadIdx.x & 31;
    int o = blockIdx.x * 8 + warp;
    int b = blockIdx.y;
    const float* wr = w1 + (size_t)o * 3072 + 1024;
    const float* gb = g + b * 2048;
    float a = 0.f;
    for (int j = lane; j < 2048; j += 32) a = fmaf(wr[j], gb[j], a);
    #pragma unroll
    for (int off = 16; off > 0; off >>= 1) a += __shfl_xor_sync(0xffffffffu, a, off);
    if (lane == 0) beff[b * 512 + o] = bias1[o] + a;
}

// ---------------- cls3: warp per point --------------------------------------
__global__ void cls3_kernel(const __half* __restrict__ c2, const float* __restrict__ w3,
                            const float* __restrict__ b3, float* __restrict__ out) {
    __shared__ float ws[NCLS * 256];
    int tid = threadIdx.x;
    for (int i = tid; i < NCLS * 256; i += 256) ws[i] = w3[i];
    __syncthreads();
    int warp = tid >> 5, lane = tid & 31;
    int p = blockIdx.x * 8 + warp;
    int b = p >> 12, n = p & (NPTS - 1);
    float xr[8];
    #pragma unroll
    for (int i = 0; i < 8; i++) xr[i] = __half2float(c2[(size_t)p * 256 + lane + i * 32]);
    #pragma unroll
    for (int j = 0; j < NCLS; j++) {
        float a = 0.f;
        #pragma unroll
        for (int i = 0; i < 8; i++) a = fmaf(ws[j * 256 + lane + i * 32], xr[i], a);
        #pragma unroll
        for (int off = 16; off > 0; off >>= 1) a += __shfl_xor_sync(0xffffffffu, a, off);
        if (lane == 0) out[((size_t)b * NCLS + j) * NPTS + n] = a + b3[j];
    }
}

// ---------------- launcher --------------------------------------------------
extern "C" void kernel_launch(void* const* d_in, const int* in_sizes, int n_in,
                              void* d_out, int out_size) {
    const float* in_inputs  = (const float*)d_in[0];
    const float* emb_w1     = (const float*)d_in[1];
    const float* emb_s1     = (const float*)d_in[2];
    const float* emb_b1     = (const float*)d_in[3];
    const float* emb_w2     = (const float*)d_in[4];
    const float* emb_s2     = (const float*)d_in[5];
    const float* emb_b2     = (const float*)d_in[6];
    const float* blk_wq     = (const float*)d_in[7];
    const float* blk_wk     = (const float*)d_in[8];
    const float* blk_wv     = (const float*)d_in[9];
    const float* blk_wpos   = (const float*)d_in[10];
    const float* blk_wo     = (const float*)d_in[11];
    const float* blk_s      = (const float*)d_in[12];
    const float* blk_b      = (const float*)d_in[13];
    const float* fuse_w     = (const float*)d_in[14];
    const float* fuse_s     = (const float*)d_in[15];
    const float* fuse_b     = (const float*)d_in[16];
    const float* cls_w1     = (const float*)d_in[17];
    const float* cls_bias1  = (const float*)d_in[18];
    const float* cls_s1     = (const float*)d_in[19];
    const float* cls_sh1    = (const float*)d_in[20];
    const float* cls_w2     = (const float*)d_in[21];
    const float* cls_bias2  = (const float*)d_in[22];
    const float* cls_s2     = (const float*)d_in[23];
    const float* cls_sh2    = (const float*)d_in[24];
    const float* cls_w3     = (const float*)d_in[25];
    const float* cls_bias3  = (const float*)d_in[26];

    float* pool = nullptr;
    cudaGetSymbolAddress((void**)&pool, g_pool);
    int*    idx   = (int*)(pool + OFF_IDX);
    __half* e1    = (__half*)(pool + OFF_E1);
    __half* xcur  = (__half*)(pool + OFF_XCUR);
    __half* qkvb  = (__half*)(pool + OFF_QKV);
    __half* aggb  = (__half*)(pool + OFF_AGG);
    __half* xcat  = (__half*)(pool + OFF_XCAT);
    __half* fuse  = (__half*)(pool + OFF_FUSE);
    float*  g     = pool + OFF_G;
    float*  beff  = pool + OFF_BEFF;
    __half* c1    = (__half*)(pool + OFF_C1);
    __half* c2    = (__half*)(pool + OFF_C2);
    __half* we2   = (__half*)(pool + OFF_WE2);
    __half* wqkv  = (__half*)(pool + OFF_WQKV);
    __half* wwo   = (__half*)(pool + OFF_WWO);
    __half* wfuse = (__half*)(pool + OFF_WFUSE);
    __half* wc1   = (__half*)(pool + OFF_WC1);
    __half* wc2   = (__half*)(pool + OFF_WC2);
    float*  gpart = pool + OFF_GPART;
    float*  outp  = (float*)d_out;

    const int SMEM2 = 3 * (128 * 128 + 8192);  // 73728 (BM=128)
    const int SMEM1 = 3 * (64 * 128 + 8192);   // 49152 (BM=64)
    cudaFuncSetAttribute(gemm_hmma_kernel<2, false>, cudaFuncAttributeMaxDynamicSharedMemorySize, SMEM2);
    cudaFuncSetAttribute(gemm_hmma_kernel<2, true>,  cudaFuncAttributeMaxDynamicSharedMemorySize, SMEM2);
    cudaFuncSetAttribute(gemm_hmma_kernel<1, false>, cudaFuncAttributeMaxDynamicSharedMemorySize, SMEM1);

    // launch order: 0-based index 3 = attn0 (ncu capture slot)
    pack_all_kernel<<<NBE + NBK, 256>>>(in_inputs, emb_w1, emb_s1, emb_b1, emb_w2,
        blk_wq, blk_wk, blk_wv, blk_wo, fuse_w, cls_w1, cls_w2,
        we2, wqkv, wwo, wfuse, wc1, wc2, e1, idx);                               // 0
    gemm_hmma_kernel<1, false><<<dim3(PTOT / 64, 2), 256, SMEM1>>>(e1, we2, nullptr, nullptr,
        emb_s2, emb_b2, nullptr, xcur, nullptr, CH, CH, 0, CH, CH, 0, 1, nullptr); // 1
    gemm_hmma_kernel<2, false><<<dim3(PTOT / 128, 6), 256, SMEM2>>>(xcur,          // 2
        wqkv, nullptr, nullptr, nullptr, nullptr, nullptr,
        qkvb, nullptr, CH, CH, 0, 384, 384, 0, 0, nullptr);

    for (int i = 0; i < 3; i++) {
        if (i > 0) {
            gemm_hmma_kernel<2, false><<<dim3(PTOT / 128, 6), 256, SMEM2>>>(
                xcat + (size_t)(i - 1) * CH,
                wqkv + (size_t)i * 384 * CH, nullptr, nullptr, nullptr, nullptr, nullptr,
                qkvb, nullptr, CH, 3 * CH, 0, 384, 384, 0, 0, nullptr);
        }
        attn_agg_kernel<<<PTOT / 2, 128>>>(qkvb, idx, in_inputs,                 // 3 on i=0
                                           blk_wpos + (size_t)i * CH * 3, aggb);
        const __half* rsd = (i == 0) ? xcur : (xcat + (size_t)(i - 1) * CH);
        int ldr = (i == 0) ? CH : 3 * CH;
        gemm_hmma_kernel<1, false><<<dim3(PTOT / 64, 2), 256, SMEM1>>>(aggb,
            wwo + (size_t)i * CH * CH, nullptr, nullptr,
            blk_s + (size_t)i * CH, blk_b + (size_t)i * CH,
            rsd, xcat + (size_t)i * CH, nullptr, CH, CH, ldr, CH, 3 * CH, 0, 1, nullptr);
    }

    // fuse 384 -> 1024 (leaky) with pooled epilogue partials
    gemm_hmma_kernel<2, true><<<dim3(PTOT / 128, 16), 256, SMEM2>>>(xcat, wfuse,
        nullptr, nullptr, fuse_s, fuse_b, nullptr, fuse, nullptr,
        384, 384, 0, 1024, 1024, 0, 2, gpart);

    gfinal_kernel<<<16, 256>>>(gpart, g);
    beff_kernel<<<dim3(64, BATCH), 256>>>(cls_w1, cls_bias1, g, beff);

    gemm_hmma_kernel<2, false><<<dim3(PTOT / 128, 8), 256, SMEM2>>>(fuse, wc1, nullptr, beff,
        cls_s1, cls_sh1, nullptr, c1, nullptr, 1024, 1024, 0, 512, 512, 0, 1, nullptr);
    gemm_hmma_kernel<2, false><<<dim3(PTOT / 128, 4), 256, SMEM2>>>(c1, wc2, cls_bias2, nullptr,
        cls_s2, cls_sh2, nullptr, c2, nullptr, 512, 512, 0, 256, 256, 0, 1, nullptr);
    cls3_kernel<<<PTOT / 8, 256>>>(c2, cls_w3, cls_bias3, outp);
}

// round 17
// speedup vs baseline: 1.0655x; 1.0655x over previous
#include <cuda_runtime.h>
#include <cuda_fp16.h>
#include <math.h>
#include <float.h>
#include <stdint.h>

#define BATCH 4
#define NPTS 4096
#define PTOT (BATCH * NPTS)
#define KNNK 16
#define CIN 9
#define CH 128
#define NCLS 13

__device__ __forceinline__ uint32_t s2u(const void* p) {
    return (uint32_t)__cvta_generic_to_shared(p);
}
__device__ __forceinline__ void ldsm4(uint32_t* r, uint32_t a) {
    asm volatile("ldmatrix.sync.aligned.m8n8.x4.shared.b16 {%0,%1,%2,%3}, [%4];"
                 : "=r"(r[0]), "=r"(r[1]), "=r"(r[2]), "=r"(r[3]) : "r"(a));
}
__device__ __forceinline__ void mma16816(float* d, const uint32_t* a, const uint32_t* b) {
    asm volatile("mma.sync.aligned.m16n8k16.row.col.f32.f16.f16.f32 "
                 "{%0,%1,%2,%3}, {%4,%5,%6,%7}, {%8,%9}, {%0,%1,%2,%3};"
                 : "+f"(d[0]), "+f"(d[1]), "+f"(d[2]), "+f"(d[3])
                 : "r"(a[0]), "r"(a[1]), "r"(a[2]), "r"(a[3]), "r"(b[0]), "r"(b[1]));
}
// monotone float<->uint key (for atomicMax on signed floats)
__device__ __forceinline__ unsigned fkey(float f) {
    unsigned u = __float_as_uint(f);
    return (u & 0x80000000u) ? ~u : (u | 0x80000000u);
}
__device__ __forceinline__ float funkey(unsigned k) {
    unsigned u = (k & 0x80000000u) ? (k & 0x7fffffffu) : ~k;
    return __uint_as_float(u);
}

// ---------------- scratch pool (floats) -------------------------------------
#define OFF_IDX   0
#define OFF_E1    (OFF_IDX  + PTOT * 16)
#define OFF_XCUR  (OFF_E1   + PTOT * 64)
#define OFF_QKV   (OFF_XCUR + PTOT * 64)
#define OFF_AGG   (OFF_QKV  + PTOT * 192)
#define OFF_XCAT  (OFF_AGG  + PTOT * 64)
#define OFF_FUSE  (OFF_XCAT + PTOT * 192)
#define OFF_G     (OFF_FUSE + PTOT * 512)
#define OFF_BEFF  (OFF_G    + BATCH * 2048)
#define OFF_C1    (OFF_BEFF + BATCH * 512)
#define OFF_C2    (OFF_C1   + PTOT * 256)
#define OFF_WE2   (OFF_C2   + PTOT * 128)
#define OFF_WQKV  (OFF_WE2  + 8192)
#define OFF_WWO   (OFF_WQKV + 73728)
#define OFF_WFUSE (OFF_WWO  + 24576)
#define OFF_WC1   (OFF_WFUSE + 196608)
#define OFF_WC2   (OFF_WC1  + 262144)
#define OFF_GPART (OFF_WC2  + 65536)        // 2 * 4*1024*32 = 262144
#define POOL_SZ   (OFF_GPART + 262144)

__device__ __align__(16) float g_pool[POOL_SZ];

// ---------------- KNN device routine (one warp per point) -------------------
__device__ void knn_warp(const float* __restrict__ in, int* __restrict__ idxo,
                         int gw, int lane) {
    int b = gw >> 12, n = gw & (NPTS - 1);
    const float* xb = in + (size_t)b * CIN * NPTS;
    float x0 = xb[n], y0 = xb[NPTS + n], z0 = xb[2 * NPTS + n];
    float sq0 = x0 * x0 + y0 * y0 + z0 * z0;
    float dl[KNNK]; int il[KNNK];
    #pragma unroll
    for (int t = 0; t < KNNK; t++) { dl[t] = FLT_MAX; il[t] = 0x7fffffff; }
    float worst = FLT_MAX;
    for (int i = 0; i < NPTS / 32; i++) {
        int m = i * 32 + lane;
        float xm = xb[m], ym = xb[NPTS + m], zm = xb[2 * NPTS + m];
        float sqm = xm * xm + ym * ym + zm * zm;
        float dot = x0 * xm + y0 * ym + z0 * zm;
        float dm = sq0 + sqm - 2.0f * dot;
        if (dm < worst) {
            bool done = false;
            #pragma unroll
            for (int t = 0; t < KNNK; t++)
                if (!done && dl[t] == worst) { dl[t] = dm; il[t] = m; done = true; }
            worst = dl[0];
            #pragma unroll
            for (int t = 1; t < KNNK; t++) worst = fmaxf(worst, dl[t]);
        }
    }
    int* op = idxo + (size_t)gw * KNNK;
    for (int t = 0; t < KNNK; t++) {
        float lm = dl[0]; int li = il[0];
        #pragma unroll
        for (int j = 1; j < KNNK; j++)
            if (dl[j] < lm || (dl[j] == lm && il[j] < li)) { lm = dl[j]; li = il[j]; }
        float bm = lm; int bi = li;
        #pragma unroll
        for (int off = 16; off > 0; off >>= 1) {
            float om = __shfl_down_sync(0xffffffffu, bm, off);
            int   oi = __shfl_down_sync(0xffffffffu, bi, off);
            if (om < bm || (om == bm && oi < bi)) { bm = om; bi = oi; }
        }
        bm = __shfl_sync(0xffffffffu, bm, 0);
        bi = __shfl_sync(0xffffffffu, bi, 0);
        if (lane == 0) op[t] = bi;
        if (bi == li && bm == lm) {
            #pragma unroll
            for (int j = 0; j < KNNK; j++) if (il[j] == bi) dl[j] = FLT_MAX;
        }
    }
}

// ---------------- fused pack + emb1 + knn kernel ----------------------------
#define PS0 16384
#define PS1 (PS0 + 147456)
#define PS2 (PS1 + 49152)
#define PS3 (PS2 + 393216)
#define PS4 (PS3 + 524288)
#define PS5 (PS4 + 131072)
#define PS6 (PS5 + PTOT * 128)
#define NBE (PS6 / 256)
#define NBK (PTOT / 8)
__global__ void pack_all_kernel(
    const float* __restrict__ inp,
    const float* __restrict__ e1w, const float* __restrict__ e1s, const float* __restrict__ e1b,
    const float* __restrict__ e2w,
    const float* __restrict__ wq, const float* __restrict__ wk, const float* __restrict__ wv,
    const float* __restrict__ wo, const float* __restrict__ fw,
    const float* __restrict__ c1w, const float* __restrict__ c2w,
    __half* __restrict__ we2, __half* __restrict__ wqkv,
    __half* __restrict__ wwo, __half* __restrict__ wfuse,
    __half* __restrict__ wc1, __half* __restrict__ wc2,
    __half* __restrict__ e1, int* __restrict__ idxo) {
    if (blockIdx.x >= NBE) {
        int gw = (blockIdx.x - NBE) * 8 + (threadIdx.x >> 5);
        knn_warp(inp, idxo, gw, threadIdx.x & 31);
        return;
    }
    int i = blockIdx.x * 256 + threadIdx.x;
    if (i < PS0) {
        we2[i] = __float2half(e2w[i]);
    } else if (i < PS1) {
        int j = i - PS0;
        int blk = j / 49152, t = j % 49152;
        int o = t / CH, k = t % CH;
        const float* src = (o < CH) ? wq : (o < 2 * CH) ? wk : wv;
        int oo = o & (CH - 1);
        wqkv[j] = __float2half(src[(size_t)blk * CH * CH + (size_t)oo * CH + k]);
    } else if (i < PS2) {
        int j = i - PS1;
        wwo[j] = __float2half(wo[j]);
    } else if (i < PS3) {
        int j = i - PS2;
        wfuse[j] = __float2half(fw[j]);
    } else if (i < PS4) {
        int j = i - PS3;
        int o = j >> 10, k = j & 1023;
        wc1[j] = __float2half(c1w[(size_t)o * 3072 + k]);
    } else if (i < PS5) {
        int j = i - PS4;
        wc2[j] = __float2half(c2w[j]);
    } else {
        int j = i - PS5;
        int o = j & 127, p = j >> 7;
        int b = p >> 12, n = p & (NPTS - 1);
        const float* xb = inp + (size_t)b * CIN * NPTS + n;
        const float* wr = e1w + o * CIN;
        float acc = 0.f;
        #pragma unroll
        for (int c = 0; c < CIN; c++) acc = fmaf(wr[c], xb[(size_t)c * NPTS], acc);
        float z = fmaxf(e1s[o] * acc + e1b[o], 0.f);
        e1[j] = __float2half(z);
    }
}

// ---------------- fp16 HMMA GEMM (Kd%64==0), hoisted ptrs, half2 epilogue ---
template<int MT, bool POOL>
__global__ __launch_bounds__(256, 3)
void gemm_hmma_kernel(const __half* __restrict__ X, const __half* __restrict__ W,
                      const float* __restrict__ b1, const float* __restrict__ addb,
                      const float* __restrict__ s, const float* __restrict__ sh,
                      const __half* __restrict__ resid,
                      __half* __restrict__ out,
                      int Kd, int ldx, int ldr, int Od, int ldo, int act,
                      float* __restrict__ gpart) {
    const int BM = MT * 64;
    const int A_BYTES = BM * 128;
    const int STAGE = A_BYTES + 8192;
    const int AIT = MT * 2;          // A cp.async per thread per stage
    extern __shared__ char smem[];
    uint32_t sb = s2u(smem);
    int tid = threadIdx.x;
    int m0 = blockIdx.x * BM, o0 = blockIdx.y * 64;
    int warp = tid >> 5, lane = tid & 31;
    int warpM = warp & 3, warpN = warp >> 2;
    float acc[MT][4][4];
    #pragma unroll
    for (int a = 0; a < MT; a++)
        #pragma unroll
        for (int bq = 0; bq < 4; bq++)
            #pragma unroll
            for (int c = 0; c < 4; c++) acc[a][bq][c] = 0.f;

    int nkb = Kd >> 6;   // Kd % 64 == 0 for all call sites

    // hoisted per-thread load addresses (advance by kb*64 halves each stage)
    const __half* aSrc[AIT]; uint32_t aDst[AIT];
    #pragma unroll
    for (int it = 0; it < AIT; it++) {
        int idx = tid + it * 256;
        int r = idx >> 3, j = idx & 7;
        aDst[it] = r * 128 + ((j ^ (r & 7)) << 4);
        aSrc[it] = X + (size_t)(m0 + r) * ldx + j * 8;
    }
    const __half* bSrc[2]; uint32_t bDst[2];
    #pragma unroll
    for (int it = 0; it < 2; it++) {
        int idx = tid + it * 256;
        int r = idx >> 3, j = idx & 7;
        bDst[it] = r * 128 + ((j ^ (r & 7)) << 4);
        bSrc[it] = W + (size_t)(o0 + r) * Kd + j * 8;
    }

    auto load_stage = [&](int kb, int buf) {
        uint32_t smA = sb + buf * STAGE;
        uint32_t smB = smA + A_BYTES;
        int koff = kb << 6;
        #pragma unroll
        for (int it = 0; it < AIT; it++)
            asm volatile("cp.async.ca.shared.global [%0], [%1], 16;"
                         :: "r"(smA + aDst[it]), "l"(aSrc[it] + koff));
        #pragma unroll
        for (int it = 0; it < 2; it++)
            asm volatile("cp.async.ca.shared.global [%0], [%1], 16;"
                         :: "r"(smB + bDst[it]), "l"(bSrc[it] + koff));
        asm volatile("cp.async.commit_group;");
    };

    load_stage(0, 0);
    if (nkb > 1) load_stage(1, 1);

    for (int kb = 0; kb < nkb; kb++) {
        int buf = kb % 3;
        if (kb + 1 < nkb) asm volatile("cp.async.wait_group 1;");
        else              asm volatile("cp.async.wait_group 0;");
        __syncthreads();
        if (kb + 2 < nkb) load_stage(kb + 2, (kb + 2) % 3);
        uint32_t smA = sb + buf * STAGE;
        uint32_t smB = smA + A_BYTES;

        uint32_t bbuf[2][4][2];
        auto loadB = [&](int kk, int sel) {
            int brow = (lane & 7) + ((lane >> 4) << 3);
            int bjc = (kk >> 3) + ((lane >> 3) & 1);
            #pragma unroll
            for (int nh = 0; nh < 2; nh++) {
                int nr = warpN * 32 + nh * 16 + brow;
                uint32_t r4[4];
                ldsm4(r4, smB + nr * 128 + ((bjc ^ (nr & 7)) << 4));
                bbuf[sel][nh * 2][0] = r4[0]; bbuf[sel][nh * 2][1] = r4[1];
                bbuf[sel][nh * 2 + 1][0] = r4[2]; bbuf[sel][nh * 2 + 1][1] = r4[3];
            }
        };
        loadB(0, 0);
        #pragma unroll
        for (int step = 0; step < 4; step++) {
            int kk = step * 16;
            uint32_t a[MT][4];
            int arow = lane & 15;
            int ajc = (kk >> 3) + (lane >> 4);
            #pragma unroll
            for (int mt = 0; mt < MT; mt++) {
                int mr = warpM * (MT * 16) + mt * 16 + arow;
                ldsm4(a[mt], smA + mr * 128 + ((ajc ^ (mr & 7)) << 4));
            }
            if (step < 3) loadB(kk + 16, (step + 1) & 1);
            #pragma unroll
            for (int mt = 0; mt < MT; mt++)
                #pragma unroll
                for (int nt = 0; nt < 4; nt++)
                    mma16816(acc[mt][nt], a[mt], bbuf[step & 1][nt]);
        }
        __syncthreads();
    }

    // epilogue (half2 stores)
    float lmax[POOL ? 8 : 1], lsum[POOL ? 8 : 1];
    if (POOL) {
        #pragma unroll
        for (int ci = 0; ci < 8; ci++) { lmax[ci] = -FLT_MAX; lsum[ci] = 0.f; }
    }
    int r0w = warpM * (MT * 16) + (lane >> 2);
    int c0w = o0 + warpN * 32 + (lane & 3) * 2;
    #pragma unroll
    for (int mt = 0; mt < MT; mt++) {
        #pragma unroll
        for (int i2 = 0; i2 < 2; i2++) {
            int row = m0 + r0w + mt * 16 + i2 * 8;
            int bidx = row >> 12;
            #pragma unroll
            for (int nt = 0; nt < 4; nt++) {
                int o = c0w + nt * 8;
                float zz[2];
                #pragma unroll
                for (int j = 0; j < 2; j++) {
                    float y = acc[mt][nt][i2 * 2 + j];
                    float pre = y + (b1 ? b1[o + j] : 0.f) + (addb ? addb[bidx * Od + o + j] : 0.f);
                    float z = (s ? s[o + j] : 1.f) * pre + (sh ? sh[o + j] : 0.f);
                    if (act == 1) z = fmaxf(z, 0.f);
                    else if (act == 2) z = (z > 0.f) ? z : 0.2f * z;
                    zz[j] = z;
                }
                if (resid) {
                    half2 rv = *(const half2*)&resid[(size_t)row * ldr + o];
                    float2 rf = __half22float2(rv);
                    zz[0] += rf.x; zz[1] += rf.y;
                }
                if (POOL) {
                    #pragma unroll
                    for (int j = 0; j < 2; j++) {
                        int ci = nt * 2 + j;
                        lmax[ci] = fmaxf(lmax[ci], zz[j]);
                        lsum[ci] += zz[j];
                    }
                }
                *(half2*)&out[(size_t)row * ldo + o] = __floats2half2_rn(zz[0], zz[1]);
            }
        }
    }
    if (POOL) {
        unsigned* smax = (unsigned*)smem;
        float* ssum = (float*)smem + 64;
        if (tid < 64) { smax[tid] = 0u; ssum[tid] = 0.f; }
        __syncthreads();
        #pragma unroll
        for (int ci = 0; ci < 8; ci++) {
            int col = warpN * 32 + (lane & 3) * 2 + (ci >> 1) * 8 + (ci & 1);
            atomicMax(&smax[col], fkey(lmax[ci]));
            atomicAdd(&ssum[col], lsum[ci]);
        }
        __syncthreads();
        if (tid < 64) {
            int b = m0 >> 12, mi = (m0 >> 7) & 31;
            int o = o0 + tid;
            size_t base = (size_t)(b * 1024 + o) * 32 + mi;
            gpart[base] = funkey(smax[tid]);
            gpart[131072 + base] = ssum[tid];
        }
    }
}

// ---------------- reduce pooled partials (deterministic order) --------------
__global__ void gfinal_kernel(const float* __restrict__ gpart, float* __restrict__ g) {
    int i = blockIdx.x * 256 + threadIdx.x;   // b*1024+ch, 4096 total
    if (i >= 4096) return;
    const float* pm = gpart + (size_t)i * 32;
    const float* ps = gpart + 131072 + (size_t)i * 32;
    float mx = -FLT_MAX, sm = 0.f;
    #pragma unroll
    for (int t = 0; t < 32; t++) { mx = fmaxf(mx, pm[t]); sm += ps[t]; }
    int b = i >> 10, ch = i & 1023;
    g[b * 2048 + ch] = mx;
    g[b * 2048 + 1024 + ch] = sm * (1.f / 4096.f);
}

// ---------------- attention: 2 points / 128-thread block, half2 -------------
__global__ __launch_bounds__(128)
void attn_agg_kernel(const __half* __restrict__ qkv, const int* __restrict__ idx,
                     const float* __restrict__ in, const float* __restrict__ wpos,
                     __half* __restrict__ agg) {
    int tid = threadIdx.x;
    int h = tid >> 6;
    int l = tid & 63;
    int w2 = l >> 5, lane = l & 31;
    int p = blockIdx.x * 2 + h;
    int b = p >> 12, n = p & (NPTS - 1);
    __shared__ float attnS[2][KNNK], slogS[2][KNNK], relS[2][KNNK][3];
    __shared__ int sIdxS[2][KNNK];

    if (l < KNNK) sIdxS[h][l] = idx[(size_t)p * KNNK + l];
    const half2* q2p = (const half2*)(qkv + (size_t)p * 384);
    half2 q2[2];
    q2[0] = q2p[lane];
    q2[1] = q2p[lane + 32];
    __syncthreads();

    const float* xb = in + (size_t)b * CIN * NPTS;
    #pragma unroll
    for (int i = 0; i < 8; i++) {
        int kk = w2 * 8 + i;
        int m = sIdxS[h][kk];
        const half2* k2p = (const half2*)(qkv + ((size_t)b * NPTS + m) * 384 + CH);
        float d = 0.f;
        #pragma unroll
        for (int u = 0; u < 2; u++) {
            float2 fq = __half22float2(q2[u]);
            float2 fk = __half22float2(k2p[lane + 32 * u]);
            d = fmaf(fq.x, fk.x, d);
            d = fmaf(fq.y, fk.y, d);
        }
        #pragma unroll
        for (int st = 16; st > 0; st >>= 1) d += __shfl_down_sync(0xffffffffu, d, st);
        if (lane == 0) slogS[h][kk] = d * 0.08838834764831845f;
        if (lane < 3)  relS[h][kk][lane] = xb[lane * NPTS + n] - xb[lane * NPTS + m];
    }
    __syncthreads();
    if (w2 == 0) {
        float sv = (lane < KNNK) ? slogS[h][lane] : -FLT_MAX;
        float mx = sv;
        #pragma unroll
        for (int off = 8; off > 0; off >>= 1)
            mx = fmaxf(mx, __shfl_xor_sync(0xffffffffu, mx, off));
        float e = (lane < KNNK) ? expf(sv - mx) : 0.f;
        float sum = e;
        #pragma unroll
        for (int off = 8; off > 0; off >>= 1)
            sum += __shfl_xor_sync(0xffffffffu, sum, off);
        if (lane < KNNK) attnS[h][lane] = e / sum;
    }
    __syncthreads();
    int t = l;
    float w00 = wpos[(2 * t) * 3 + 0], w01 = wpos[(2 * t) * 3 + 1], w02 = wpos[(2 * t) * 3 + 2];
    float w10 = wpos[(2 * t + 1) * 3 + 0], w11 = wpos[(2 * t + 1) * 3 + 1], w12 = wpos[(2 * t + 1) * 3 + 2];
    float a0 = 0.f, a1 = 0.f;
    #pragma unroll
    for (int kk = 0; kk < KNNK; kk++) {
        int m = sIdxS[h][kk];
        float aw = attnS[h][kk];
        float r0 = relS[h][kk][0], r1 = relS[h][kk][1], r2 = relS[h][kk][2];
        half2 v2 = ((const half2*)qkv)[(size_t)(b * NPTS + m) * 192 + 128 + t];
        float2 fv = __half22float2(v2);
        float vn0 = fv.x + w00 * r0 + w01 * r1 + w02 * r2;
        float vn1 = fv.y + w10 * r0 + w11 * r1 + w12 * r2;
        a0 = fmaf(aw, vn0, a0);
        a1 = fmaf(aw, vn1, a1);
    }
    ((half2*)agg)[(size_t)p * 64 + t] = __floats2half2_rn(a0, a1);
}

// ------- fold global features into per-(b,o) cls1 bias (warp per o) ---------
__global__ void beff_kernel(const float* __restrict__ w1, const float* __restrict__ bias1,
                            const float* __restrict__ g, float* __restrict__ beff) {
    int warp = threadIdx.x >> 5, lane = threadIdx.x & 31;
    int o = blockIdx.x * 8 + warp;
    int b = blockIdx.y;
    const float* wr = w1 + (size_t)o * 3072 + 1024;
    const float* gb = g + b * 2048;
    float a = 0.f;
    for (int j = lane; j < 2048; j += 32) a = fmaf(wr[j], gb[j], a);
    #pragma unroll
    for (int off = 16; off > 0; off >>= 1) a += __shfl_xor_sync(0xffffffffu, a, off);
    if (lane == 0) beff[b * 512 + o] = bias1[o] + a;
}

// ---------------- cls3: warp per point --------------------------------------
__global__ void cls3_kernel(const __half* __restrict__ c2, const float* __restrict__ w3,
                            const float* __restrict__ b3, float* __restrict__ out) {
    __shared__ float ws[NCLS * 256];
    int tid = threadIdx.x;
    for (int i = tid; i < NCLS * 256; i += 256) ws[i] = w3[i];
    __syncthreads();
    int warp = tid >> 5, lane = tid & 31;
    int p = blockIdx.x * 8 + warp;
    int b = p >> 12, n = p & (NPTS - 1);
    float xr[8];
    #pragma unroll
    for (int i = 0; i < 8; i++) xr[i] = __half2float(c2[(size_t)p * 256 + lane + i * 32]);
    #pragma unroll
    for (int j = 0; j < NCLS; j++) {
        float a = 0.f;
        #pragma unroll
        for (int i = 0; i < 8; i++) a = fmaf(ws[j * 256 + lane + i * 32], xr[i], a);
        #pragma unroll
        for (int off = 16; off > 0; off >>= 1) a += __shfl_xor_sync(0xffffffffu, a, off);
        if (lane == 0) out[((size_t)b * NCLS + j) * NPTS + n] = a + b3[j];
    }
}

// ---------------- launcher --------------------------------------------------
extern "C" void kernel_launch(void* const* d_in, const int* in_sizes, int n_in,
                              void* d_out, int out_size) {
    const float* in_inputs  = (const float*)d_in[0];
    const float* emb_w1     = (const float*)d_in[1];
    const float* emb_s1     = (const float*)d_in[2];
    const float* emb_b1     = (const float*)d_in[3];
    const float* emb_w2     = (const float*)d_in[4];
    const float* emb_s2     = (const float*)d_in[5];
    const float* emb_b2     = (const float*)d_in[6];
    const float* blk_wq     = (const float*)d_in[7];
    const float* blk_wk     = (const float*)d_in[8];
    const float* blk_wv     = (const float*)d_in[9];
    const float* blk_wpos   = (const float*)d_in[10];
    const float* blk_wo     = (const float*)d_in[11];
    const float* blk_s      = (const float*)d_in[12];
    const float* blk_b      = (const float*)d_in[13];
    const float* fuse_w     = (const float*)d_in[14];
    const float* fuse_s     = (const float*)d_in[15];
    const float* fuse_b     = (const float*)d_in[16];
    const float* cls_w1     = (const float*)d_in[17];
    const float* cls_bias1  = (const float*)d_in[18];
    const float* cls_s1     = (const float*)d_in[19];
    const float* cls_sh1    = (const float*)d_in[20];
    const float* cls_w2     = (const float*)d_in[21];
    const float* cls_bias2  = (const float*)d_in[22];
    const float* cls_s2     = (const float*)d_in[23];
    const float* cls_sh2    = (const float*)d_in[24];
    const float* cls_w3     = (const float*)d_in[25];
    const float* cls_bias3  = (const float*)d_in[26];

    float* pool = nullptr;
    cudaGetSymbolAddress((void**)&pool, g_pool);
    int*    idx   = (int*)(pool + OFF_IDX);
    __half* e1    = (__half*)(pool + OFF_E1);
    __half* xcur  = (__half*)(pool + OFF_XCUR);
    __half* qkvb  = (__half*)(pool + OFF_QKV);
    __half* aggb  = (__half*)(pool + OFF_AGG);
    __half* xcat  = (__half*)(pool + OFF_XCAT);
    __half* fuse  = (__half*)(pool + OFF_FUSE);
    float*  g     = pool + OFF_G;
    float*  beff  = pool + OFF_BEFF;
    __half* c1    = (__half*)(pool + OFF_C1);
    __half* c2    = (__half*)(pool + OFF_C2);
    __half* we2   = (__half*)(pool + OFF_WE2);
    __half* wqkv  = (__half*)(pool + OFF_WQKV);
    __half* wwo   = (__half*)(pool + OFF_WWO);
    __half* wfuse = (__half*)(pool + OFF_WFUSE);
    __half* wc1   = (__half*)(pool + OFF_WC1);
    __half* wc2   = (__half*)(pool + OFF_WC2);
    float*  gpart = pool + OFF_GPART;
    float*  outp  = (float*)d_out;

    const int SMEM2 = 3 * (128 * 128 + 8192);  // 73728 (BM=128)
    const int SMEM1 = 3 * (64 * 128 + 8192);   // 49152 (BM=64)
    cudaFuncSetAttribute(gemm_hmma_kernel<2, false>, cudaFuncAttributeMaxDynamicSharedMemorySize, SMEM2);
    cudaFuncSetAttribute(gemm_hmma_kernel<2, true>,  cudaFuncAttributeMaxDynamicSharedMemorySize, SMEM2);
    cudaFuncSetAttribute(gemm_hmma_kernel<1, false>, cudaFuncAttributeMaxDynamicSharedMemorySize, SMEM1);

    // launch order: 0-based index 3 = attn0 (ncu capture slot)
    pack_all_kernel<<<NBE + NBK, 256>>>(in_inputs, emb_w1, emb_s1, emb_b1, emb_w2,
        blk_wq, blk_wk, blk_wv, blk_wo, fuse_w, cls_w1, cls_w2,
        we2, wqkv, wwo, wfuse, wc1, wc2, e1, idx);                               // 0
    gemm_hmma_kernel<1, false><<<dim3(PTOT / 64, 2), 256, SMEM1>>>(e1, we2, nullptr, nullptr,
        emb_s2, emb_b2, nullptr, xcur, CH, CH, 0, CH, CH, 1, nullptr);           // 1
    gemm_hmma_kernel<2, false><<<dim3(PTOT / 128, 6), 256, SMEM2>>>(xcur,        // 2
        wqkv, nullptr, nullptr, nullptr, nullptr, nullptr,
        qkvb, CH, CH, 0, 384, 384, 0, nullptr);

    for (int i = 0; i < 3; i++) {
        if (i > 0) {
            gemm_hmma_kernel<2, false><<<dim3(PTOT / 128, 6), 256, SMEM2>>>(
                xcat + (size_t)(i - 1) * CH,
                wqkv + (size_t)i * 384 * CH, nullptr, nullptr, nullptr, nullptr, nullptr,
                qkvb, CH, 3 * CH, 0, 384, 384, 0, nullptr);
        }
        attn_agg_kernel<<<PTOT / 2, 128>>>(qkvb, idx, in_inputs,                 // 3 on i=0
                                           blk_wpos + (size_t)i * CH * 3, aggb);
        const __half* rsd = (i == 0) ? xcur : (xcat + (size_t)(i - 1) * CH);
        int ldr = (i == 0) ? CH : 3 * CH;
        gemm_hmma_kernel<1, false><<<dim3(PTOT / 64, 2), 256, SMEM1>>>(aggb,
            wwo + (size_t)i * CH * CH, nullptr, nullptr,
            blk_s + (size_t)i * CH, blk_b + (size_t)i * CH,
            rsd, xcat + (size_t)i * CH, CH, CH, ldr, CH, 3 * CH, 1, nullptr);
    }

    // fuse 384 -> 1024 (leaky) with pooled epilogue partials
    gemm_hmma_kernel<2, true><<<dim3(PTOT / 128, 16), 256, SMEM2>>>(xcat, wfuse,
        nullptr, nullptr, fuse_s, fuse_b, nullptr, fuse,
        384, 384, 0, 1024, 1024, 2, gpart);

    gfinal_kernel<<<16, 256>>>(gpart, g);
    beff_kernel<<<dim3(64, BATCH), 256>>>(cls_w1, cls_bias1, g, beff);

    gemm_hmma_kernel<2, false><<<dim3(PTOT / 128, 8), 256, SMEM2>>>(fuse, wc1, nullptr, beff,
        cls_s1, cls_sh1, nullptr, c1, 1024, 1024, 0, 512, 512, 1, nullptr);
    gemm_hmma_kernel<2, false><<<dim3(PTOT / 128, 4), 256, SMEM2>>>(c1, wc2, cls_bias2, nullptr,
        cls_s2, cls_sh2, nullptr, c2, 512, 512, 0, 256, 256, 1, nullptr);
    cls3_kernel<<<PTOT / 8, 256>>>(c2, cls_w3, cls_bias3, outp);
}